// round 4
// baseline (speedup 1.0000x reference)
#include <cuda_runtime.h>
#include <cuda_fp16.h>

// Problem constants (fixed by the dataset)
#define N_TOTAL   10000
#define NUM_ATOMS 100
#define N_EDGES   1000000
#define NCL 38
#define NFL 12

#define EDGE_BLOCKS  148
#define EDGE_THREADS 512
#define EPT 4
// chunk per block: multiple of 4 (keeps int4/longlong2 loads aligned, no tail)
#define EDGE_CHUNK 6760   // 148 * 6760 = 1,000,480 >= 1,000,000

#define SMEM_NA_BYTES (N_TOTAL * 16)            // 160,000
#define SMEM_EA_BYTES (N_TOTAL * 4)             // 40,000
#define SMEM_TOTAL_BYTES (SMEM_NA_BYTES + SMEM_EA_BYTES)

// Scratch (alloc-free rule: __device__ globals)
__device__ float4 g_NA[N_TOTAL];   // {x, a(i-role), b(j-role), half2(sin,cos)}
__device__ float  g_wc[NCL];
__device__ float  g_wf[NFL];
__device__ int    g_e64;           // 1 if edge_index is int64, 0 if int32

__device__ __forceinline__ float safe_inv_f(float v) {
    float w = (fabsf(v) < 0.01f) ? ((v >= 0.0f) ? 0.01f : -0.01f) : v;
    return __fdividef(1.0f, w);
}

// ---------------- fused setup: weights collapse + parallel dtype probe ----------------
__global__ void setup_kernel(const float* __restrict__ c_mask,
                             const float* __restrict__ f_mask,
                             const float* __restrict__ wc2,
                             const float* __restrict__ wf2,
                             const void* eidx_raw) {
    int k = threadIdx.x;
    if (k < NCL) g_wc[k] = c_mask[k] * (wc2[k] - wc2[k + NCL]);
    if (k < NFL) g_wf[k] = f_mask[k] * (wf2[k] - wf2[k + NFL]);
    if (k < 32) {
        // probe 64 int64 words in parallel: valid int64 indices iff all in range
        const long long* p = (const long long*)eidx_raw;
        long long v0 = p[k];
        long long v1 = p[k + 32];
        int ok = (v0 >= 0 && v0 < N_TOTAL && v1 >= 0 && v1 < N_TOTAL) ? 1 : 0;
        unsigned m = __ballot_sync(0xFFFFFFFFu, ok);
        if (k == 0) g_e64 = (m == 0xFFFFFFFFu) ? 1 : 0;
    }
}

// ---------------- node pass: F(x) -> out, plus packed per-node table ----------------
__global__ void node_kernel(const float* __restrict__ x, float* __restrict__ out) {
    int n = blockIdx.x * blockDim.x + threadIdx.x;
    if (n >= N_TOTAL) return;
    float xv = x[n];
    float s, c;
    __sincosf(xv, &s, &c);
    float E = __expf(-xv);
    float R = __expf(xv);
    float inv  = safe_inv_f(xv);
    float inv2 = inv * inv;
    float th = (R - E) * __fdividef(1.0f, R + E);     // tanh(x)
    float sg = __fdividef(1.0f, 1.0f + E);            // sigmoid(x)
    float rl = fmaxf(xv, 0.0f);
    float x2 = xv * xv;

    const float* wf = g_wf;
    float F = wf[0]
            + wf[1]*s + wf[2]*c + wf[3]*xv*s
            + wf[4]*xv + wf[5]*x2
            + wf[6]*inv + wf[7]*inv2 + wf[8]*inv2*inv
            + wf[9]*th + wf[10]*sg + wf[11]*rl;
    out[n] = F;   // F_COEF = 1; edge kernel accumulates on top

    const float* wc = g_wc;
    // node-as-x_i contribution (feature idx 0,3,6,10,18,19,26,27,28)
    float a = wc[0]*xv + wc[3]*x2 + wc[6]*inv + wc[10]*inv2
            + wc[18]*s + wc[19]*c + wc[26]*th + wc[27]*sg + wc[28]*rl;
    // node-as-x_j contribution (feature idx 1,4,7,11,20,21,29,30,31)
    float b = wc[1]*xv + wc[4]*x2 + wc[7]*inv + wc[11]*inv2
            + wc[20]*s + wc[21]*c + wc[29]*th + wc[30]*sg + wc[31]*rl;

    __half2 sc = __floats2half2_rn(s, c);
    g_NA[n] = make_float4(xv, a, b, __uint_as_float(*reinterpret_cast<unsigned*>(&sc)));
}

// ---------------- edge pass: smem-staged tables + segment-sum atomics ----------------
__global__ void __launch_bounds__(EDGE_THREADS)
edge_kernel(const void* __restrict__ eidx_raw,
            const float* __restrict__ edge_attr,
            float* __restrict__ out) {
    extern __shared__ unsigned char sm_raw[];
    float4* sNA = reinterpret_cast<float4*>(sm_raw);
    float*  sEA = reinterpret_cast<float*>(sm_raw + SMEM_NA_BYTES);

    // ---- stage node table + edge_attr into smem (coalesced float4) ----
    for (int i = threadIdx.x; i < N_TOTAL; i += EDGE_THREADS)
        sNA[i] = g_NA[i];
    {
        const float4* ea4 = reinterpret_cast<const float4*>(edge_attr);
        float4* sea4 = reinterpret_cast<float4*>(sEA);
        for (int i = threadIdx.x; i < N_TOTAL / 4; i += EDGE_THREADS)
            sea4[i] = ea4[i];
    }

    // effective coupled weights (uniform; read while staging is in flight)
    const float wd1  = g_wc[2],  wd2  = g_wc[5];
    const float wid  = g_wc[8],  wis  = g_wc[9],  wid2 = g_wc[12], wis2 = g_wc[13];
    const float wsd  = g_wc[14], wcd  = g_wc[15], wss  = g_wc[16], wcs  = g_wc[17];
    const float wxx  = g_wc[22], wxsj = g_wc[23], wxsi = g_wc[24], wsdcs = g_wc[25];
    const float wthd = g_wc[32], wsgd = g_wc[33], wrld = g_wc[34];
    const float wths = g_wc[35], wsgs = g_wc[36], wrls = g_wc[37];
    const int e64 = g_e64;

    __syncthreads();

    int start = blockIdx.x * EDGE_CHUNK;
    int end   = min(start + EDGE_CHUNK, N_EDGES);

    for (int e0 = start + (threadIdx.x << 2); e0 < end; e0 += (EDGE_THREADS << 2)) {
        // start and N_EDGES are multiples of 4 -> full quad always valid
        int js[EPT], is[EPT];
        if (e64) {
            const long long* e = (const long long*)eidx_raw;
            longlong2 s0 = *reinterpret_cast<const longlong2*>(e + e0);
            longlong2 s1 = *reinterpret_cast<const longlong2*>(e + e0 + 2);
            longlong2 d0 = *reinterpret_cast<const longlong2*>(e + N_EDGES + e0);
            longlong2 d1 = *reinterpret_cast<const longlong2*>(e + N_EDGES + e0 + 2);
            js[0] = (int)s0.x; js[1] = (int)s0.y; js[2] = (int)s1.x; js[3] = (int)s1.y;
            is[0] = (int)d0.x; is[1] = (int)d0.y; is[2] = (int)d1.x; is[3] = (int)d1.y;
        } else {
            const int* e = (const int*)eidx_raw;
            int4 sp = *reinterpret_cast<const int4*>(e + e0);
            int4 dp = *reinterpret_cast<const int4*>(e + N_EDGES + e0);
            js[0] = sp.x; js[1] = sp.y; js[2] = sp.z; js[3] = sp.w;
            is[0] = dp.x; is[1] = dp.y; is[2] = dp.z; is[3] = dp.w;
        }

        // ---- batch all smem gathers (hide LDS latency) ----
        float4 Nj[EPT], Ni[EPT];
        float  ea[EPT];
#pragma unroll
        for (int k = 0; k < EPT; k++) {
            Nj[k] = sNA[js[k]];
            Ni[k] = sNA[is[k]];
        }
#pragma unroll
        for (int k = 0; k < EPT; k++)
            ea[k] = sEA[(js[k] % NUM_ATOMS) * NUM_ATOMS + (is[k] % NUM_ATOMS)];

#pragma unroll
        for (int k = 0; k < EPT; k++) {
            float xi = Ni[k].x, ai = Ni[k].y;
            float xj = Nj[k].x, bj = Nj[k].z;
            unsigned ui = __float_as_uint(Ni[k].w);
            unsigned uj = __float_as_uint(Nj[k].w);
            float2 sci = __half22float2(*reinterpret_cast<__half2*>(&ui));
            float2 scj = __half22float2(*reinterpret_cast<__half2*>(&uj));
            float si = sci.x, ci = sci.y;
            float sj = scj.x, cj = scj.y;

            float d  = xj - xi;
            float sm = xj + xi;

            // trig of d and s via angle-sum identities
            float p1 = sj * ci, p2 = cj * si, p3 = ci * cj, p4 = si * sj;
            float sind = p1 - p2, sins = p1 + p2;
            float cosd = p3 + p4, coss = p3 - p4;

            float invd = safe_inv_f(d);
            float invs = safe_inv_f(sm);

            // activations of d and s via per-edge exp (MUFU is cheap)
            float vd  = __expf(-d);
            float vs  = __expf(-sm);
            float vd2 = vd * vd, vs2 = vs * vs;
            float thd = (1.0f - vd2) * __fdividef(1.0f, 1.0f + vd2);
            float sgd = __fdividef(1.0f, 1.0f + vd);
            float ths = (1.0f - vs2) * __fdividef(1.0f, 1.0f + vs2);
            float sgs = __fdividef(1.0f, 1.0f + vs);

            float core = ai + bj;
            core = fmaf(wd1,  d,            core);
            core = fmaf(wd2,  d * d,        core);
            core = fmaf(wid,  invd,         core);
            core = fmaf(wid2, invd * invd,  core);
            core = fmaf(wis,  invs,         core);
            core = fmaf(wis2, invs * invs,  core);
            core = fmaf(wsd,  sind,         core);
            core = fmaf(wcd,  cosd,         core);
            core = fmaf(wss,  sins,         core);
            core = fmaf(wcs,  coss,         core);
            core = fmaf(wxx,  xi * xj,      core);
            core = fmaf(wxsj, xi * sj,      core);
            core = fmaf(wxsi, xj * si,      core);
            core = fmaf(wsdcs, sind * coss, core);
            core = fmaf(wthd, thd,          core);
            core = fmaf(wsgd, sgd,          core);
            core = fmaf(wrld, fmaxf(d, 0.0f),  core);
            core = fmaf(wths, ths,          core);
            core = fmaf(wsgs, sgs,          core);
            core = fmaf(wrls, fmaxf(sm, 0.0f), core);

            atomicAdd(&out[is[k]], ea[k] * core);   // segment_sum over dst
        }
    }
}

extern "C" void kernel_launch(void* const* d_in, const int* in_sizes, int n_in,
                              void* d_out, int out_size) {
    // Identify inputs by element count (robust to whether scalar `t` occupies
    // a slot). Reference order: t?, x[10000], edge_index[2000000], c_mask[38],
    // f_mask[12], wc_2[76], wf_2[24], edge_attr_all[10000].
    const float* x   = nullptr;
    const void*  ei  = nullptr;
    const float* cm  = nullptr;
    const float* fm  = nullptr;
    const float* wc2 = nullptr;
    const float* wf2 = nullptr;
    const float* ea  = nullptr;
    for (int idx = 0; idx < n_in; idx++) {
        int s = in_sizes[idx];
        if (s == 2 * N_EDGES)      ei  = d_in[idx];
        else if (s == NCL)         cm  = (const float*)d_in[idx];
        else if (s == NFL)         fm  = (const float*)d_in[idx];
        else if (s == 2 * NCL)     wc2 = (const float*)d_in[idx];
        else if (s == 2 * NFL)     wf2 = (const float*)d_in[idx];
        else if (s == N_TOTAL) {
            if (!x) x = (const float*)d_in[idx];   // x comes first
            else    ea = (const float*)d_in[idx];  // edge_attr_all second
        }
    }
    float* out = (float*)d_out;

    static int smem_set = 0;   // idempotent attribute set (host-side, capture-safe)
    if (!smem_set) {
        cudaFuncSetAttribute(edge_kernel,
                             cudaFuncAttributeMaxDynamicSharedMemorySize,
                             SMEM_TOTAL_BYTES);
        smem_set = 1;
    }

    setup_kernel<<<1, 64>>>(cm, fm, wc2, wf2, ei);
    node_kernel<<<(N_TOTAL + 255) / 256, 256>>>(x, out);
    edge_kernel<<<EDGE_BLOCKS, EDGE_THREADS, SMEM_TOTAL_BYTES>>>(ei, ea, out);
}

// round 5
// speedup vs baseline: 1.1625x; 1.1625x over previous
#include <cuda_runtime.h>
#include <cuda_fp16.h>

// Problem constants (fixed by the dataset)
#define N_TOTAL   10000
#define NUM_ATOMS 100
#define N_EDGES   1000000
#define NCL 38
#define NFL 12

#define EDGE_BLOCKS  296          // 2 per SM
#define EDGE_THREADS 512
#define EPT 4
#define EDGE_CHUNK 3380           // 296 * 3380 = 1,000,480 >= 1e6; multiple of 4

// Scratch (alloc-free rule: __device__ globals)
__device__ float4 g_NA[N_TOTAL];   // {x, a(i-role), b(j-role), half2(sin,cos)}

__device__ __forceinline__ float safe_inv_f(float v) {
    float w = (fabsf(v) < 0.01f) ? ((v >= 0.0f) ? 0.01f : -0.01f) : v;
    return __fdividef(1.0f, w);
}

// ---------------- node pass: F(x) -> out, plus packed per-node table ----------------
// Weight collapse done per-block in smem (no separate setup kernel).
__global__ void node_kernel(const float* __restrict__ x,
                            const float* __restrict__ c_mask,
                            const float* __restrict__ f_mask,
                            const float* __restrict__ wc2,
                            const float* __restrict__ wf2,
                            float* __restrict__ out) {
    __shared__ float swc[NCL];
    __shared__ float swf[NFL];
    int t = threadIdx.x;
    if (t < NCL) swc[t] = c_mask[t] * (wc2[t] - wc2[t + NCL]);
    if (t < NFL) swf[t] = f_mask[t] * (wf2[t] - wf2[t + NFL]);
    __syncthreads();

    int n = blockIdx.x * blockDim.x + t;
    if (n >= N_TOTAL) return;
    float xv = x[n];
    float s, c;
    __sincosf(xv, &s, &c);
    float E = __expf(-xv);
    float R = __expf(xv);
    float inv  = safe_inv_f(xv);
    float inv2 = inv * inv;
    float th = (R - E) * __fdividef(1.0f, R + E);     // tanh(x)
    float sg = __fdividef(1.0f, 1.0f + E);            // sigmoid(x)
    float rl = fmaxf(xv, 0.0f);
    float x2 = xv * xv;

    float F = swf[0]
            + swf[1]*s + swf[2]*c + swf[3]*xv*s
            + swf[4]*xv + swf[5]*x2
            + swf[6]*inv + swf[7]*inv2 + swf[8]*inv2*inv
            + swf[9]*th + swf[10]*sg + swf[11]*rl;
    out[n] = F;   // F_COEF = 1; edge kernel accumulates on top

    // node-as-x_i contribution (feature idx 0,3,6,10,18,19,26,27,28)
    float a = swc[0]*xv + swc[3]*x2 + swc[6]*inv + swc[10]*inv2
            + swc[18]*s + swc[19]*c + swc[26]*th + swc[27]*sg + swc[28]*rl;
    // node-as-x_j contribution (feature idx 1,4,7,11,20,21,29,30,31)
    float b = swc[1]*xv + swc[4]*x2 + swc[7]*inv + swc[11]*inv2
            + swc[20]*s + swc[21]*c + swc[29]*th + swc[30]*sg + swc[31]*rl;

    __half2 sc = __floats2half2_rn(s, c);
    g_NA[n] = make_float4(xv, a, b, __uint_as_float(*reinterpret_cast<unsigned*>(&sc)));
}

// ---------------- edge pass: L1 node gathers + smem ea + segment-sum atomics ----------------
__global__ void __launch_bounds__(EDGE_THREADS, 2)
edge_kernel(const void* __restrict__ eidx_raw,
            const float* __restrict__ c_mask,
            const float* __restrict__ wc2,
            const float* __restrict__ edge_attr,
            float* __restrict__ out) {
    __shared__ float sEA[N_TOTAL];     // 40 KB: edge_attr_all
    __shared__ float sW[NCL];
    __shared__ int   sE64;

    int t = threadIdx.x;
    // per-block weight collapse (redundant across blocks; deterministic)
    if (t < NCL) sW[t] = c_mask[t] * (wc2[t] - wc2[t + NCL]);
    // per-block dtype probe: 64 int64 words all in [0,N_TOTAL) <=> genuine int64
    if (t >= 64 && t < 96) {
        int k = t - 64;
        const long long* p = (const long long*)eidx_raw;
        long long v0 = p[k];
        long long v1 = p[k + 32];
        int ok = (v0 >= 0 && v0 < N_TOTAL && v1 >= 0 && v1 < N_TOTAL) ? 1 : 0;
        unsigned m = __ballot_sync(0xFFFFFFFFu, ok);
        if (k == 0) sE64 = (m == 0xFFFFFFFFu) ? 1 : 0;
    }
    // stage edge_attr into smem (coalesced float4)
    {
        const float4* ea4 = reinterpret_cast<const float4*>(edge_attr);
        float4* sea4 = reinterpret_cast<float4*>(sEA);
        for (int i = t; i < N_TOTAL / 4; i += EDGE_THREADS)
            sea4[i] = ea4[i];
    }
    __syncthreads();

    // uniform weights via smem broadcast
    const float wd1  = sW[2],  wd2  = sW[5];
    const float wid  = sW[8],  wis  = sW[9],  wid2 = sW[12], wis2 = sW[13];
    const float wsd  = sW[14], wcd  = sW[15], wss  = sW[16], wcs  = sW[17];
    const float wxx  = sW[22], wxsj = sW[23], wxsi = sW[24], wsdcs = sW[25];
    const float wthd = sW[32], wsgd = sW[33], wrld = sW[34];
    const float wths = sW[35], wsgs = sW[36], wrls = sW[37];
    const int e64 = sE64;

    int start = blockIdx.x * EDGE_CHUNK;
    int end   = min(start + EDGE_CHUNK, N_EDGES);

    for (int e0 = start + (t << 2); e0 < end; e0 += (EDGE_THREADS << 2)) {
        // start and end are multiples of 4 -> full quad always valid
        int js[EPT], is[EPT];
        if (e64) {
            const long long* e = (const long long*)eidx_raw;
            longlong2 s0 = *reinterpret_cast<const longlong2*>(e + e0);
            longlong2 s1 = *reinterpret_cast<const longlong2*>(e + e0 + 2);
            longlong2 d0 = *reinterpret_cast<const longlong2*>(e + N_EDGES + e0);
            longlong2 d1 = *reinterpret_cast<const longlong2*>(e + N_EDGES + e0 + 2);
            js[0] = (int)s0.x; js[1] = (int)s0.y; js[2] = (int)s1.x; js[3] = (int)s1.y;
            is[0] = (int)d0.x; is[1] = (int)d0.y; is[2] = (int)d1.x; is[3] = (int)d1.y;
        } else {
            const int* e = (const int*)eidx_raw;
            int4 sp = *reinterpret_cast<const int4*>(e + e0);
            int4 dp = *reinterpret_cast<const int4*>(e + N_EDGES + e0);
            js[0] = sp.x; js[1] = sp.y; js[2] = sp.z; js[3] = sp.w;
            is[0] = dp.x; is[1] = dp.y; is[2] = dp.z; is[3] = dp.w;
        }

        // ---- issue all node-table gathers up front (max MLP, L1-resident) ----
        float4 Nj[EPT], Ni[EPT];
        float  ea[EPT];
#pragma unroll
        for (int k = 0; k < EPT; k++) {
            Nj[k] = __ldg(&g_NA[js[k]]);
            Ni[k] = __ldg(&g_NA[is[k]]);
        }
#pragma unroll
        for (int k = 0; k < EPT; k++)
            ea[k] = sEA[(js[k] % NUM_ATOMS) * NUM_ATOMS + (is[k] % NUM_ATOMS)];

#pragma unroll
        for (int k = 0; k < EPT; k++) {
            float xi = Ni[k].x, ai = Ni[k].y;
            float xj = Nj[k].x, bj = Nj[k].z;
            unsigned ui = __float_as_uint(Ni[k].w);
            unsigned uj = __float_as_uint(Nj[k].w);
            float2 sci = __half22float2(*reinterpret_cast<__half2*>(&ui));
            float2 scj = __half22float2(*reinterpret_cast<__half2*>(&uj));
            float si = sci.x, ci = sci.y;
            float sj = scj.x, cj = scj.y;

            float d  = xj - xi;
            float sm = xj + xi;

            // trig of d and s via angle-sum identities
            float p1 = sj * ci, p2 = cj * si, p3 = ci * cj, p4 = si * sj;
            float sind = p1 - p2, sins = p1 + p2;
            float cosd = p3 + p4, coss = p3 - p4;

            float invd = safe_inv_f(d);
            float invs = safe_inv_f(sm);

            // activations of d and s via per-edge exp (MUFU is cheap)
            float vd  = __expf(-d);
            float vs  = __expf(-sm);
            float vd2 = vd * vd, vs2 = vs * vs;
            float thd = (1.0f - vd2) * __fdividef(1.0f, 1.0f + vd2);
            float sgd = __fdividef(1.0f, 1.0f + vd);
            float ths = (1.0f - vs2) * __fdividef(1.0f, 1.0f + vs2);
            float sgs = __fdividef(1.0f, 1.0f + vs);

            float core = ai + bj;
            core = fmaf(wd1,  d,            core);
            core = fmaf(wd2,  d * d,        core);
            core = fmaf(wid,  invd,         core);
            core = fmaf(wid2, invd * invd,  core);
            core = fmaf(wis,  invs,         core);
            core = fmaf(wis2, invs * invs,  core);
            core = fmaf(wsd,  sind,         core);
            core = fmaf(wcd,  cosd,         core);
            core = fmaf(wss,  sins,         core);
            core = fmaf(wcs,  coss,         core);
            core = fmaf(wxx,  xi * xj,      core);
            core = fmaf(wxsj, xi * sj,      core);
            core = fmaf(wxsi, xj * si,      core);
            core = fmaf(wsdcs, sind * coss, core);
            core = fmaf(wthd, thd,          core);
            core = fmaf(wsgd, sgd,          core);
            core = fmaf(wrld, fmaxf(d, 0.0f),  core);
            core = fmaf(wths, ths,          core);
            core = fmaf(wsgs, sgs,          core);
            core = fmaf(wrls, fmaxf(sm, 0.0f), core);

            atomicAdd(&out[is[k]], ea[k] * core);   // segment_sum over dst
        }
    }
}

extern "C" void kernel_launch(void* const* d_in, const int* in_sizes, int n_in,
                              void* d_out, int out_size) {
    // Identify inputs by element count (robust to whether scalar `t` occupies
    // a slot). Reference order: t?, x[10000], edge_index[2000000], c_mask[38],
    // f_mask[12], wc_2[76], wf_2[24], edge_attr_all[10000].
    const float* x   = nullptr;
    const void*  ei  = nullptr;
    const float* cm  = nullptr;
    const float* fm  = nullptr;
    const float* wc2 = nullptr;
    const float* wf2 = nullptr;
    const float* ea  = nullptr;
    for (int idx = 0; idx < n_in; idx++) {
        int s = in_sizes[idx];
        if (s == 2 * N_EDGES)      ei  = d_in[idx];
        else if (s == NCL)         cm  = (const float*)d_in[idx];
        else if (s == NFL)         fm  = (const float*)d_in[idx];
        else if (s == 2 * NCL)     wc2 = (const float*)d_in[idx];
        else if (s == 2 * NFL)     wf2 = (const float*)d_in[idx];
        else if (s == N_TOTAL) {
            if (!x) x = (const float*)d_in[idx];   // x comes first
            else    ea = (const float*)d_in[idx];  // edge_attr_all second
        }
    }
    float* out = (float*)d_out;

    node_kernel<<<(N_TOTAL + 255) / 256, 256>>>(x, cm, fm, wc2, wf2, out);
    edge_kernel<<<EDGE_BLOCKS, EDGE_THREADS>>>(ei, cm, wc2, ea, out);
}

// round 6
// speedup vs baseline: 1.1641x; 1.0014x over previous
#include <cuda_runtime.h>
#include <cuda_fp16.h>

// Problem constants (fixed by the dataset)
#define N_TOTAL   10000
#define NUM_ATOMS 100
#define N_EDGES   1000000
#define NCL 38
#define NFL 12

#define EDGE_BLOCKS  740          // 5 per SM
#define EDGE_THREADS 256
#define EPT 2
#define EDGE_CHUNK 1352           // 740 * 1352 = 1,000,480 >= 1e6; even

// Scratch (alloc-free rule: __device__ globals)
__device__ float4 g_NA[N_TOTAL];   // {x, a(i-role), b(j-role), half2(sin,cos)}

__device__ __forceinline__ float safe_inv_f(float v) {
    float w = (fabsf(v) < 0.01f) ? ((v >= 0.0f) ? 0.01f : -0.01f) : v;
    return __fdividef(1.0f, w);
}

// ---------------- node pass: F(x) -> out, plus packed per-node table ----------------
__global__ void node_kernel(const float* __restrict__ x,
                            const float* __restrict__ c_mask,
                            const float* __restrict__ f_mask,
                            const float* __restrict__ wc2,
                            const float* __restrict__ wf2,
                            float* __restrict__ out) {
    __shared__ float swc[NCL];
    __shared__ float swf[NFL];
    int t = threadIdx.x;
    if (t < NCL) swc[t] = c_mask[t] * (wc2[t] - wc2[t + NCL]);
    if (t < NFL) swf[t] = f_mask[t] * (wf2[t] - wf2[t + NFL]);
    __syncthreads();

    int n = blockIdx.x * blockDim.x + t;
    if (n >= N_TOTAL) return;
    float xv = x[n];
    float s, c;
    __sincosf(xv, &s, &c);
    float E = __expf(-xv);
    float R = __expf(xv);
    float inv  = safe_inv_f(xv);
    float inv2 = inv * inv;
    float th = (R - E) * __fdividef(1.0f, R + E);     // tanh(x)
    float sg = __fdividef(1.0f, 1.0f + E);            // sigmoid(x)
    float rl = fmaxf(xv, 0.0f);
    float x2 = xv * xv;

    float F = swf[0]
            + swf[1]*s + swf[2]*c + swf[3]*xv*s
            + swf[4]*xv + swf[5]*x2
            + swf[6]*inv + swf[7]*inv2 + swf[8]*inv2*inv
            + swf[9]*th + swf[10]*sg + swf[11]*rl;
    out[n] = F;   // F_COEF = 1; edge kernel accumulates on top

    // node-as-x_i contribution (feature idx 0,3,6,10,18,19,26,27,28)
    float a = swc[0]*xv + swc[3]*x2 + swc[6]*inv + swc[10]*inv2
            + swc[18]*s + swc[19]*c + swc[26]*th + swc[27]*sg + swc[28]*rl;
    // node-as-x_j contribution (feature idx 1,4,7,11,20,21,29,30,31)
    float b = swc[1]*xv + swc[4]*x2 + swc[7]*inv + swc[11]*inv2
            + swc[20]*s + swc[21]*c + swc[29]*th + swc[30]*sg + swc[31]*rl;

    __half2 sc = __floats2half2_rn(s, c);
    g_NA[n] = make_float4(xv, a, b, __uint_as_float(*reinterpret_cast<unsigned*>(&sc)));
}

// ---------------- edge pass: all-L1 gathers + segment-sum atomics ----------------
__global__ void __launch_bounds__(EDGE_THREADS, 5)
edge_kernel(const void* __restrict__ eidx_raw,
            const float* __restrict__ c_mask,
            const float* __restrict__ wc2,
            const float* __restrict__ edge_attr,
            float* __restrict__ out) {
    __shared__ float sW[NCL];
    __shared__ int   sE64;

    int t = threadIdx.x;
    // per-block weight collapse (redundant across blocks; deterministic)
    if (t < NCL) sW[t] = c_mask[t] * (wc2[t] - wc2[t + NCL]);
    // per-block dtype probe: 64 int64 words all in [0,N_TOTAL) <=> genuine int64
    if (t >= 64 && t < 96) {
        int k = t - 64;
        const long long* p = (const long long*)eidx_raw;
        long long v0 = p[k];
        long long v1 = p[k + 32];
        int ok = (v0 >= 0 && v0 < N_TOTAL && v1 >= 0 && v1 < N_TOTAL) ? 1 : 0;
        unsigned m = __ballot_sync(0xFFFFFFFFu, ok);
        if (k == 0) sE64 = (m == 0xFFFFFFFFu) ? 1 : 0;
    }
    __syncthreads();

    const float wd1  = sW[2],  wd2  = sW[5];
    const float wid  = sW[8],  wis  = sW[9],  wid2 = sW[12], wis2 = sW[13];
    const float wsd  = sW[14], wcd  = sW[15], wss  = sW[16], wcs  = sW[17];
    const float wxx  = sW[22], wxsj = sW[23], wxsi = sW[24], wsdcs = sW[25];
    const float wthd = sW[32], wsgd = sW[33], wrld = sW[34];
    const float wths = sW[35], wsgs = sW[36], wrls = sW[37];
    const int e64 = sE64;

    int start = blockIdx.x * EDGE_CHUNK;
    int end   = min(start + EDGE_CHUNK, N_EDGES);

    for (int e0 = start + (t << 1); e0 < end; e0 += (EDGE_THREADS << 1)) {
        // start/end even -> both edges of the pair always valid
        int js[EPT], is[EPT];
        if (e64) {
            const long long* e = (const long long*)eidx_raw;
            longlong2 s0 = __ldcs(reinterpret_cast<const longlong2*>(e + e0));
            longlong2 d0 = __ldcs(reinterpret_cast<const longlong2*>(e + N_EDGES + e0));
            js[0] = (int)s0.x; js[1] = (int)s0.y;
            is[0] = (int)d0.x; is[1] = (int)d0.y;
        } else {
            const int* e = (const int*)eidx_raw;
            int2 sp = __ldcs(reinterpret_cast<const int2*>(e + e0));
            int2 dp = __ldcs(reinterpret_cast<const int2*>(e + N_EDGES + e0));
            js[0] = sp.x; js[1] = sp.y;
            is[0] = dp.x; is[1] = dp.y;
        }

        // ---- issue all gathers up front (L1-resident table + ea) ----
        float4 Nj[EPT], Ni[EPT];
        float  ea[EPT];
#pragma unroll
        for (int k = 0; k < EPT; k++) {
            Nj[k] = __ldg(&g_NA[js[k]]);
            Ni[k] = __ldg(&g_NA[is[k]]);
        }
#pragma unroll
        for (int k = 0; k < EPT; k++)
            ea[k] = __ldg(&edge_attr[(js[k] % NUM_ATOMS) * NUM_ATOMS + (is[k] % NUM_ATOMS)]);

#pragma unroll
        for (int k = 0; k < EPT; k++) {
            float xi = Ni[k].x, ai = Ni[k].y;
            float xj = Nj[k].x, bj = Nj[k].z;
            unsigned ui = __float_as_uint(Ni[k].w);
            unsigned uj = __float_as_uint(Nj[k].w);
            float2 sci = __half22float2(*reinterpret_cast<__half2*>(&ui));
            float2 scj = __half22float2(*reinterpret_cast<__half2*>(&uj));
            float si = sci.x, ci = sci.y;
            float sj = scj.x, cj = scj.y;

            float d  = xj - xi;
            float sm = xj + xi;

            // trig of d and s via angle-sum identities
            float p1 = sj * ci, p2 = cj * si, p3 = ci * cj, p4 = si * sj;
            float sind = p1 - p2, sins = p1 + p2;
            float cosd = p3 + p4, coss = p3 - p4;

            float invd = safe_inv_f(d);
            float invs = safe_inv_f(sm);

            // activations of d and s via per-edge exp (MUFU is cheap)
            float vd  = __expf(-d);
            float vs  = __expf(-sm);
            float vd2 = vd * vd, vs2 = vs * vs;
            float thd = (1.0f - vd2) * __fdividef(1.0f, 1.0f + vd2);
            float sgd = __fdividef(1.0f, 1.0f + vd);
            float ths = (1.0f - vs2) * __fdividef(1.0f, 1.0f + vs2);
            float sgs = __fdividef(1.0f, 1.0f + vs);

            float core = ai + bj;
            core = fmaf(wd1,  d,            core);
            core = fmaf(wd2,  d * d,        core);
            core = fmaf(wid,  invd,         core);
            core = fmaf(wid2, invd * invd,  core);
            core = fmaf(wis,  invs,         core);
            core = fmaf(wis2, invs * invs,  core);
            core = fmaf(wsd,  sind,         core);
            core = fmaf(wcd,  cosd,         core);
            core = fmaf(wss,  sins,         core);
            core = fmaf(wcs,  coss,         core);
            core = fmaf(wxx,  xi * xj,      core);
            core = fmaf(wxsj, xi * sj,      core);
            core = fmaf(wxsi, xj * si,      core);
            core = fmaf(wsdcs, sind * coss, core);
            core = fmaf(wthd, thd,          core);
            core = fmaf(wsgd, sgd,          core);
            core = fmaf(wrld, fmaxf(d, 0.0f),  core);
            core = fmaf(wths, ths,          core);
            core = fmaf(wsgs, sgs,          core);
            core = fmaf(wrls, fmaxf(sm, 0.0f), core);

            atomicAdd(&out[is[k]], ea[k] * core);   // segment_sum over dst
        }
    }
}

extern "C" void kernel_launch(void* const* d_in, const int* in_sizes, int n_in,
                              void* d_out, int out_size) {
    // Identify inputs by element count (robust to whether scalar `t` occupies
    // a slot). Reference order: t?, x[10000], edge_index[2000000], c_mask[38],
    // f_mask[12], wc_2[76], wf_2[24], edge_attr_all[10000].
    const float* x   = nullptr;
    const void*  ei  = nullptr;
    const float* cm  = nullptr;
    const float* fm  = nullptr;
    const float* wc2 = nullptr;
    const float* wf2 = nullptr;
    const float* ea  = nullptr;
    for (int idx = 0; idx < n_in; idx++) {
        int s = in_sizes[idx];
        if (s == 2 * N_EDGES)      ei  = d_in[idx];
        else if (s == NCL)         cm  = (const float*)d_in[idx];
        else if (s == NFL)         fm  = (const float*)d_in[idx];
        else if (s == 2 * NCL)     wc2 = (const float*)d_in[idx];
        else if (s == 2 * NFL)     wf2 = (const float*)d_in[idx];
        else if (s == N_TOTAL) {
            if (!x) x = (const float*)d_in[idx];   // x comes first
            else    ea = (const float*)d_in[idx];  // edge_attr_all second
        }
    }
    float* out = (float*)d_out;

    node_kernel<<<(N_TOTAL + 255) / 256, 256>>>(x, cm, fm, wc2, wf2, out);
    edge_kernel<<<EDGE_BLOCKS, EDGE_THREADS>>>(ei, cm, wc2, ea, out);
}